// round 1
// baseline (speedup 1.0000x reference)
#include <cuda_runtime.h>

// Problem constants
namespace {
constexpr int B = 4, L = 2048, D = 1024, H = 16, DH = 64;
constexpr int BH = B * H;    // 64
constexpr int ML = B * L;    // 8192
}

// Scratch (device globals; no allocation in kernel_launch)
__device__ float g_Qh[(size_t)B * H * L * DH];   // [B,H,L,64], pre-scaled by 1/TEMP
__device__ float g_Kh[(size_t)B * H * L * DH];
__device__ float g_Vh[(size_t)B * H * L * DH];
__device__ float g_OutH[(size_t)B * L * H * DH]; // [B*L, H*64]

// ---------------------------------------------------------------------------
// GEMM 1: projections.  Out[b,h,l,d] = (X[b,l,:] @ W[:, h*64+d] + bias)*scale
// M=8192, N=1024, K=1024.  128x128 tile, BK=16, 256 thr, 8x8 microtile.
// ---------------------------------------------------------------------------
__global__ __launch_bounds__(256) void gemm_proj(
    const float* __restrict__ X, const float* __restrict__ W,
    const float* __restrict__ bias, float* __restrict__ OutHeads, float scale)
{
    __shared__ float As[16][128];
    __shared__ float Bs[16][128];
    const int tid = threadIdx.x;
    const int m0 = blockIdx.y * 128;
    const int n0 = blockIdx.x * 128;
    const int tm = (tid / 16) * 8;
    const int tn = (tid % 16) * 8;
    float acc[8][8];
#pragma unroll
    for (int i = 0; i < 8; i++)
#pragma unroll
        for (int j = 0; j < 8; j++) acc[i][j] = 0.f;

    for (int k0 = 0; k0 < D; k0 += 16) {
#pragma unroll
        for (int t = 0; t < 2; t++) {           // A tile: 128x16 = 512 float4
            int idx = tid + t * 256;
            int row = idx >> 2;
            int c4  = idx & 3;
            float4 v = *(const float4*)(X + (size_t)(m0 + row) * D + k0 + c4 * 4);
            As[c4 * 4 + 0][row] = v.x; As[c4 * 4 + 1][row] = v.y;
            As[c4 * 4 + 2][row] = v.z; As[c4 * 4 + 3][row] = v.w;
        }
#pragma unroll
        for (int t = 0; t < 2; t++) {           // B tile: 16x128 = 512 float4
            int idx = tid + t * 256;
            int row = idx >> 5;
            int c4  = idx & 31;
            *(float4*)&Bs[row][c4 * 4] =
                *(const float4*)(W + (size_t)(k0 + row) * D + n0 + c4 * 4);
        }
        __syncthreads();
#pragma unroll
        for (int k = 0; k < 16; k++) {
            float a[8], bfr[8];
            *(float4*)&a[0]   = *(float4*)&As[k][tm];
            *(float4*)&a[4]   = *(float4*)&As[k][tm + 4];
            *(float4*)&bfr[0] = *(float4*)&Bs[k][tn];
            *(float4*)&bfr[4] = *(float4*)&Bs[k][tn + 4];
#pragma unroll
            for (int i = 0; i < 8; i++)
#pragma unroll
                for (int j = 0; j < 8; j++) acc[i][j] += a[i] * bfr[j];
        }
        __syncthreads();
    }
    // Epilogue: remap (m = b*L + l, n = h*64 + d) -> [b,h,l,d]
    const int bblk = m0 / L;          // 128 | L, tile never crosses batch
    const int lbase = m0 % L;
#pragma unroll
    for (int i = 0; i < 8; i++) {
        int l = lbase + tm + i;
#pragma unroll
        for (int j = 0; j < 8; j++) {
            int gn = n0 + tn + j;
            int h = gn >> 6, d = gn & 63;
            float val = (acc[i][j] + bias[gn]) * scale;
            OutHeads[(((size_t)bblk * H + h) * L + l) * DH + d] = val;
        }
    }
}

// ---------------------------------------------------------------------------
// GEMM 2: scores.  att_raw[bh,i,j] = mask[b,i,j] ? Qh[bh,i,:]·Kh[bh,j,:] : -1e9
// Per bh: M=N=2048, K=64 (two 32-chunks).  128x128 tile, 8x8 microtile.
// ---------------------------------------------------------------------------
__global__ __launch_bounds__(256) void gemm_scores(
    const int* __restrict__ mask, float* __restrict__ att)
{
    __shared__ float Qs[32][128];
    __shared__ float Ks[32][128];
    const int tid = threadIdx.x;
    const int bh = blockIdx.z;
    const int b  = bh / H;
    const int i0 = blockIdx.y * 128;
    const int j0 = blockIdx.x * 128;
    const float* Qb = g_Qh + (size_t)bh * L * DH;
    const float* Kb = g_Kh + (size_t)bh * L * DH;
    const int tm = (tid / 16) * 8;
    const int tn = (tid % 16) * 8;
    float acc[8][8];
#pragma unroll
    for (int i = 0; i < 8; i++)
#pragma unroll
        for (int j = 0; j < 8; j++) acc[i][j] = 0.f;

    for (int kc = 0; kc < DH; kc += 32) {
#pragma unroll
        for (int t = 0; t < 4; t++) {           // each tile 128x32 = 1024 float4
            int idx = tid + t * 256;
            int row = idx >> 3;
            int c4  = idx & 7;
            float4 v = *(const float4*)(Qb + (size_t)(i0 + row) * DH + kc + c4 * 4);
            Qs[c4 * 4 + 0][row] = v.x; Qs[c4 * 4 + 1][row] = v.y;
            Qs[c4 * 4 + 2][row] = v.z; Qs[c4 * 4 + 3][row] = v.w;
            float4 w = *(const float4*)(Kb + (size_t)(j0 + row) * DH + kc + c4 * 4);
            Ks[c4 * 4 + 0][row] = w.x; Ks[c4 * 4 + 1][row] = w.y;
            Ks[c4 * 4 + 2][row] = w.z; Ks[c4 * 4 + 3][row] = w.w;
        }
        __syncthreads();
#pragma unroll
        for (int k = 0; k < 32; k++) {
            float a[8], bfr[8];
            *(float4*)&a[0]   = *(float4*)&Qs[k][tm];
            *(float4*)&a[4]   = *(float4*)&Qs[k][tm + 4];
            *(float4*)&bfr[0] = *(float4*)&Ks[k][tn];
            *(float4*)&bfr[4] = *(float4*)&Ks[k][tn + 4];
#pragma unroll
            for (int i = 0; i < 8; i++)
#pragma unroll
                for (int j = 0; j < 8; j++) acc[i][j] += a[i] * bfr[j];
        }
        __syncthreads();
    }
    const int* mrow = mask + (size_t)b * L * L;
    float* arow = att + (size_t)bh * L * L;
#pragma unroll
    for (int i = 0; i < 8; i++) {
        int gi = i0 + tm + i;
#pragma unroll
        for (int jv = 0; jv < 2; jv++) {
            int gj = j0 + tn + jv * 4;
            int4 mk = *(const int4*)(mrow + (size_t)gi * L + gj);
            float4 o;
            o.x = mk.x ? acc[i][jv * 4 + 0] : -1e9f;
            o.y = mk.y ? acc[i][jv * 4 + 1] : -1e9f;
            o.z = mk.z ? acc[i][jv * 4 + 2] : -1e9f;
            o.w = mk.w ? acc[i][jv * 4 + 3] : -1e9f;
            *(float4*)(arow + (size_t)gi * L + gj) = o;
        }
    }
}

// ---------------------------------------------------------------------------
// Softmax: one block per row (2048 elems), 256 threads x 8 elems, in place.
// ---------------------------------------------------------------------------
__global__ __launch_bounds__(256) void softmax_rows(float* __restrict__ att)
{
    float* p = att + (size_t)blockIdx.x * L;
    const int tid = threadIdx.x;
    float4 v0 = ((const float4*)p)[tid];
    float4 v1 = ((const float4*)p)[tid + 256];

    __shared__ float red[256];
    float m = fmaxf(fmaxf(fmaxf(v0.x, v0.y), fmaxf(v0.z, v0.w)),
                    fmaxf(fmaxf(v1.x, v1.y), fmaxf(v1.z, v1.w)));
    red[tid] = m;
    __syncthreads();
#pragma unroll
    for (int s = 128; s > 0; s >>= 1) {
        if (tid < s) red[tid] = fmaxf(red[tid], red[tid + s]);
        __syncthreads();
    }
    m = red[0];
    __syncthreads();

    float4 e0, e1;
    e0.x = expf(v0.x - m); e0.y = expf(v0.y - m);
    e0.z = expf(v0.z - m); e0.w = expf(v0.w - m);
    e1.x = expf(v1.x - m); e1.y = expf(v1.y - m);
    e1.z = expf(v1.z - m); e1.w = expf(v1.w - m);
    float lsum = (e0.x + e0.y) + (e0.z + e0.w) + (e1.x + e1.y) + (e1.z + e1.w);
    red[tid] = lsum;
    __syncthreads();
#pragma unroll
    for (int s = 128; s > 0; s >>= 1) {
        if (tid < s) red[tid] += red[tid + s];
        __syncthreads();
    }
    float inv = 1.f / red[0];

    e0.x *= inv; e0.y *= inv; e0.z *= inv; e0.w *= inv;
    e1.x *= inv; e1.y *= inv; e1.z *= inv; e1.w *= inv;
    ((float4*)p)[tid]       = e0;
    ((float4*)p)[tid + 256] = e1;
}

// ---------------------------------------------------------------------------
// GEMM 3: OutH[b*L+i, h*64+d] = sum_j att[bh,i,j] * Vh[bh,j,d]
// Per bh: M=2048, N=64, K=2048.  128x64 tile, BK=32, 8x4 microtile.
// ---------------------------------------------------------------------------
__global__ __launch_bounds__(256) void gemm_av(const float* __restrict__ att)
{
    __shared__ float Ps[32][128];
    __shared__ float Vs[32][64];
    const int tid = threadIdx.x;
    const int bh = blockIdx.z;
    const int b  = bh / H, h = bh % H;
    const int i0 = blockIdx.y * 128;
    const float* Ab = att + (size_t)bh * L * L;
    const float* Vb = g_Vh + (size_t)bh * L * DH;
    const int tm = (tid / 16) * 8;
    const int tn = (tid % 16) * 4;
    float acc[8][4];
#pragma unroll
    for (int i = 0; i < 8; i++)
#pragma unroll
        for (int j = 0; j < 4; j++) acc[i][j] = 0.f;

    for (int k0 = 0; k0 < L; k0 += 32) {
#pragma unroll
        for (int t = 0; t < 4; t++) {           // P tile 128x32 = 1024 float4
            int idx = tid + t * 256;
            int row = idx >> 3;
            int c4  = idx & 7;
            float4 v = *(const float4*)(Ab + (size_t)(i0 + row) * L + k0 + c4 * 4);
            Ps[c4 * 4 + 0][row] = v.x; Ps[c4 * 4 + 1][row] = v.y;
            Ps[c4 * 4 + 2][row] = v.z; Ps[c4 * 4 + 3][row] = v.w;
        }
#pragma unroll
        for (int t = 0; t < 2; t++) {           // V tile 32x64 = 512 float4
            int idx = tid + t * 256;
            int row = idx >> 4;
            int c4  = idx & 15;
            *(float4*)&Vs[row][c4 * 4] =
                *(const float4*)(Vb + (size_t)(k0 + row) * DH + c4 * 4);
        }
        __syncthreads();
#pragma unroll
        for (int k = 0; k < 32; k++) {
            float a[8], bv[4];
            *(float4*)&a[0]  = *(float4*)&Ps[k][tm];
            *(float4*)&a[4]  = *(float4*)&Ps[k][tm + 4];
            *(float4*)&bv[0] = *(float4*)&Vs[k][tn];
#pragma unroll
            for (int i = 0; i < 8; i++)
#pragma unroll
                for (int j = 0; j < 4; j++) acc[i][j] += a[i] * bv[j];
        }
        __syncthreads();
    }
#pragma unroll
    for (int i = 0; i < 8; i++) {
        int gi = i0 + tm + i;
        float4 o = {acc[i][0], acc[i][1], acc[i][2], acc[i][3]};
        *(float4*)&g_OutH[(size_t)(b * L + gi) * D + h * DH + tn] = o;
    }
}

// ---------------------------------------------------------------------------
// GEMM 4: out = OutH @ Wfc + bfc + q   (M=8192, N=1024, K=1024)
// ---------------------------------------------------------------------------
__global__ __launch_bounds__(256) void gemm_fc(
    const float* __restrict__ Xres, const float* __restrict__ W,
    const float* __restrict__ bias, float* __restrict__ Out)
{
    __shared__ float As[16][128];
    __shared__ float Bs[16][128];
    const int tid = threadIdx.x;
    const int m0 = blockIdx.y * 128;
    const int n0 = blockIdx.x * 128;
    const int tm = (tid / 16) * 8;
    const int tn = (tid % 16) * 8;
    float acc[8][8];
#pragma unroll
    for (int i = 0; i < 8; i++)
#pragma unroll
        for (int j = 0; j < 8; j++) acc[i][j] = 0.f;

    for (int k0 = 0; k0 < D; k0 += 16) {
#pragma unroll
        for (int t = 0; t < 2; t++) {
            int idx = tid + t * 256;
            int row = idx >> 2;
            int c4  = idx & 3;
            float4 v = *(const float4*)(g_OutH + (size_t)(m0 + row) * D + k0 + c4 * 4);
            As[c4 * 4 + 0][row] = v.x; As[c4 * 4 + 1][row] = v.y;
            As[c4 * 4 + 2][row] = v.z; As[c4 * 4 + 3][row] = v.w;
        }
#pragma unroll
        for (int t = 0; t < 2; t++) {
            int idx = tid + t * 256;
            int row = idx >> 5;
            int c4  = idx & 31;
            *(float4*)&Bs[row][c4 * 4] =
                *(const float4*)(W + (size_t)(k0 + row) * D + n0 + c4 * 4);
        }
        __syncthreads();
#pragma unroll
        for (int k = 0; k < 16; k++) {
            float a[8], bfr[8];
            *(float4*)&a[0]   = *(float4*)&As[k][tm];
            *(float4*)&a[4]   = *(float4*)&As[k][tm + 4];
            *(float4*)&bfr[0] = *(float4*)&Bs[k][tn];
            *(float4*)&bfr[4] = *(float4*)&Bs[k][tn + 4];
#pragma unroll
            for (int i = 0; i < 8; i++)
#pragma unroll
                for (int j = 0; j < 8; j++) acc[i][j] += a[i] * bfr[j];
        }
        __syncthreads();
    }
#pragma unroll
    for (int i = 0; i < 8; i++) {
        int gm = m0 + tm + i;
#pragma unroll
        for (int j = 0; j < 8; j++) {
            int gn = n0 + tn + j;
            Out[(size_t)gm * D + gn] =
                acc[i][j] + bias[gn] + Xres[(size_t)gm * D + gn];
        }
    }
}

// ---------------------------------------------------------------------------
extern "C" void kernel_launch(void* const* d_in, const int* in_sizes, int n_in,
                              void* d_out, int out_size)
{
    const float* q    = (const float*)d_in[0];
    const float* k    = (const float*)d_in[1];
    const float* v    = (const float*)d_in[2];
    const int*   mask = (const int*)d_in[3];
    const float* Wq   = (const float*)d_in[4];
    const float* bq   = (const float*)d_in[5];
    const float* Wk   = (const float*)d_in[6];
    const float* bk   = (const float*)d_in[7];
    const float* Wv   = (const float*)d_in[8];
    const float* bv   = (const float*)d_in[9];
    const float* Wfc  = (const float*)d_in[10];
    const float* bfc  = (const float*)d_in[11];

    float* out = (float*)d_out;                      // [B, L, D]
    float* att = out + (size_t)B * L * D;            // [B, H, L, L]

    float *Qh = nullptr, *Kh = nullptr, *Vh = nullptr;
    cudaGetSymbolAddress((void**)&Qh, g_Qh);
    cudaGetSymbolAddress((void**)&Kh, g_Kh);
    cudaGetSymbolAddress((void**)&Vh, g_Vh);

    dim3 gp(D / 128, ML / 128);       // (8, 64)
    gemm_proj<<<gp, 256>>>(q, Wq, bq, Qh, 0.125f);   // fold 1/TEMP into Q
    gemm_proj<<<gp, 256>>>(k, Wk, bk, Kh, 1.0f);
    gemm_proj<<<gp, 256>>>(v, Wv, bv, Vh, 1.0f);

    dim3 gs(L / 128, L / 128, BH);    // (16, 16, 64)
    gemm_scores<<<gs, 256>>>(mask, att);

    softmax_rows<<<BH * L, 256>>>(att);              // 131072 rows

    dim3 ga(1, L / 128, BH);          // (1, 16, 64)
    gemm_av<<<ga, 256>>>(att);

    gemm_fc<<<gp, 256>>>(q, Wfc, bfc, out);
}

// round 2
// speedup vs baseline: 2.0735x; 2.0735x over previous
#include <cuda_runtime.h>
#include <cstdint>

// Problem constants
namespace {
constexpr int B = 4, L = 2048, D = 1024, H = 16, DH = 64;
constexpr int BH = B * H;    // 64
constexpr int ML = B * L;    // 8192
}

// Scratch (device globals; no allocation in kernel_launch)
__device__ float g_Qh[(size_t)B * H * L * DH];   // [B,H,L,64], pre-scaled by 1/TEMP
__device__ float g_Kh[(size_t)B * H * L * DH];
__device__ float g_Vh[(size_t)B * H * L * DH];
__device__ float g_OutH[(size_t)B * L * H * DH]; // [B*L, H*64]

// ---------------------------------------------------------------------------
// tf32 helpers
// ---------------------------------------------------------------------------
__device__ __forceinline__ uint32_t f2tf(float f) {
    uint32_t u;
    asm("cvt.rna.tf32.f32 %0, %1;" : "=r"(u) : "f"(f));
    return u;
}

__device__ __forceinline__ void mma8(float* c, const uint32_t* a, const uint32_t* b) {
    asm("mma.sync.aligned.m16n8k8.row.col.f32.tf32.tf32.f32 "
        "{%0,%1,%2,%3},{%4,%5,%6,%7},{%8,%9},{%0,%1,%2,%3};"
        : "+f"(c[0]), "+f"(c[1]), "+f"(c[2]), "+f"(c[3])
        : "r"(a[0]), "r"(a[1]), "r"(a[2]), "r"(a[3]), "r"(b[0]), "r"(b[1]));
}

// ---------------------------------------------------------------------------
// GEMM 1: projections.  Out[b,h,l,d] = (X[b,l,:] @ W[:, h*64+d] + bias)*scale
// M=8192, N=1024, K=1024.  Block 128x128, ktile 32, 8 warps (2x4), warp 64x32.
// A smem [m][k] pad36 (natural layout), B smem [k][n] pad132 (natural layout).
// ---------------------------------------------------------------------------
__global__ __launch_bounds__(256) void gemm_proj(
    const float* __restrict__ X, const float* __restrict__ W,
    const float* __restrict__ bias, float* __restrict__ OutHeads, float scale)
{
    __shared__ uint32_t As[128][36];
    __shared__ uint32_t Bs[32][132];
    const int tid = threadIdx.x;
    const int lane = tid & 31, w = tid >> 5;
    const int g = lane >> 2, tg = lane & 3;
    const int wm = (w >> 2) * 64;       // 0 / 64
    const int wn = (w & 3) * 32;        // 0..96
    const int m0 = blockIdx.y * 128;
    const int n0 = blockIdx.x * 128;

    float c[4][4][4];
#pragma unroll
    for (int mi = 0; mi < 4; mi++)
#pragma unroll
        for (int ni = 0; ni < 4; ni++)
#pragma unroll
            for (int r = 0; r < 4; r++) c[mi][ni][r] = 0.f;

    for (int k0 = 0; k0 < D; k0 += 32) {
#pragma unroll
        for (int t = 0; t < 4; t++) {           // A tile 128x32
            int idx = tid + t * 256;
            int row = idx >> 3, cc = (idx & 7) * 4;
            float4 v = *(const float4*)(X + (size_t)(m0 + row) * D + k0 + cc);
            As[row][cc + 0] = f2tf(v.x); As[row][cc + 1] = f2tf(v.y);
            As[row][cc + 2] = f2tf(v.z); As[row][cc + 3] = f2tf(v.w);
        }
#pragma unroll
        for (int t = 0; t < 4; t++) {           // B tile 32x128
            int idx = tid + t * 256;
            int row = idx >> 5, cc = (idx & 31) * 4;
            float4 v = *(const float4*)(W + (size_t)(k0 + row) * D + n0 + cc);
            Bs[row][cc + 0] = f2tf(v.x); Bs[row][cc + 1] = f2tf(v.y);
            Bs[row][cc + 2] = f2tf(v.z); Bs[row][cc + 3] = f2tf(v.w);
        }
        __syncthreads();
#pragma unroll
        for (int kk = 0; kk < 32; kk += 8) {
            uint32_t a[4][4], bb[4][2];
#pragma unroll
            for (int mi = 0; mi < 4; mi++) {
                int m = wm + mi * 16 + g;
                a[mi][0] = As[m][kk + tg];
                a[mi][1] = As[m + 8][kk + tg];
                a[mi][2] = As[m][kk + tg + 4];
                a[mi][3] = As[m + 8][kk + tg + 4];
            }
#pragma unroll
            for (int ni = 0; ni < 4; ni++) {
                int n = wn + ni * 8 + g;
                bb[ni][0] = Bs[kk + tg][n];
                bb[ni][1] = Bs[kk + tg + 4][n];
            }
#pragma unroll
            for (int mi = 0; mi < 4; mi++)
#pragma unroll
                for (int ni = 0; ni < 4; ni++)
                    mma8(c[mi][ni], a[mi], bb[ni]);
        }
        __syncthreads();
    }
    // Epilogue: remap (m = b*L + l, n = h*64 + d) -> [b,h,l,d]
    const int bblk = m0 / L, lbase = m0 % L;
#pragma unroll
    for (int mi = 0; mi < 4; mi++)
#pragma unroll
        for (int r = 0; r < 2; r++) {
            int l = lbase + wm + mi * 16 + g + r * 8;
#pragma unroll
            for (int ni = 0; ni < 4; ni++) {
                int n = n0 + wn + ni * 8 + tg * 2;
                int h = n >> 6, d = n & 63;
                float2 o;
                o.x = (c[mi][ni][r * 2 + 0] + bias[n]) * scale;
                o.y = (c[mi][ni][r * 2 + 1] + bias[n + 1]) * scale;
                *(float2*)&OutHeads[(((size_t)bblk * H + h) * L + l) * DH + d] = o;
            }
        }
}

// ---------------------------------------------------------------------------
// GEMM 2: scores.  att_raw[bh,i,j] = mask[b,i,j] ? Qh[bh,i,:]·Kh[bh,j,:] : -1e9
// Per bh: M=N=2048, K=64.  Block 128x128, ktile 32, warp 64x32.
// Both smem tiles natural [row][k] pad36 (B-side is "col-major" = [n][k]).
// ---------------------------------------------------------------------------
__global__ __launch_bounds__(256) void gemm_scores(
    const int* __restrict__ mask, float* __restrict__ att)
{
    __shared__ uint32_t Qs[128][36];
    __shared__ uint32_t Ks[128][36];
    const int tid = threadIdx.x;
    const int lane = tid & 31, w = tid >> 5;
    const int g = lane >> 2, tg = lane & 3;
    const int wm = (w >> 2) * 64, wn = (w & 3) * 32;
    const int bh = blockIdx.z, b = bh >> 4;
    const int i0 = blockIdx.y * 128, j0 = blockIdx.x * 128;
    const float* Qb = g_Qh + (size_t)bh * L * DH;
    const float* Kb = g_Kh + (size_t)bh * L * DH;

    float c[4][4][4];
#pragma unroll
    for (int mi = 0; mi < 4; mi++)
#pragma unroll
        for (int ni = 0; ni < 4; ni++)
#pragma unroll
            for (int r = 0; r < 4; r++) c[mi][ni][r] = 0.f;

    for (int k0 = 0; k0 < DH; k0 += 32) {
#pragma unroll
        for (int t = 0; t < 4; t++) {           // 128x32 each
            int idx = tid + t * 256;
            int row = idx >> 3, cc = (idx & 7) * 4;
            float4 v = *(const float4*)(Qb + (size_t)(i0 + row) * DH + k0 + cc);
            Qs[row][cc + 0] = f2tf(v.x); Qs[row][cc + 1] = f2tf(v.y);
            Qs[row][cc + 2] = f2tf(v.z); Qs[row][cc + 3] = f2tf(v.w);
            float4 u = *(const float4*)(Kb + (size_t)(j0 + row) * DH + k0 + cc);
            Ks[row][cc + 0] = f2tf(u.x); Ks[row][cc + 1] = f2tf(u.y);
            Ks[row][cc + 2] = f2tf(u.z); Ks[row][cc + 3] = f2tf(u.w);
        }
        __syncthreads();
#pragma unroll
        for (int kk = 0; kk < 32; kk += 8) {
            uint32_t a[4][4], bb[4][2];
#pragma unroll
            for (int mi = 0; mi < 4; mi++) {
                int m = wm + mi * 16 + g;
                a[mi][0] = Qs[m][kk + tg];
                a[mi][1] = Qs[m + 8][kk + tg];
                a[mi][2] = Qs[m][kk + tg + 4];
                a[mi][3] = Qs[m + 8][kk + tg + 4];
            }
#pragma unroll
            for (int ni = 0; ni < 4; ni++) {
                int n = wn + ni * 8 + g;
                bb[ni][0] = Ks[n][kk + tg];
                bb[ni][1] = Ks[n][kk + tg + 4];
            }
#pragma unroll
            for (int mi = 0; mi < 4; mi++)
#pragma unroll
                for (int ni = 0; ni < 4; ni++)
                    mma8(c[mi][ni], a[mi], bb[ni]);
        }
        __syncthreads();
    }
    const int* mrow = mask + (size_t)b * L * L;
    float* arow = att + (size_t)bh * L * L;
#pragma unroll
    for (int mi = 0; mi < 4; mi++)
#pragma unroll
        for (int r = 0; r < 2; r++) {
            int i = i0 + wm + mi * 16 + g + r * 8;
#pragma unroll
            for (int ni = 0; ni < 4; ni++) {
                int j = j0 + wn + ni * 8 + tg * 2;
                int2 mk = *(const int2*)(mrow + (size_t)i * L + j);
                float2 o;
                o.x = mk.x ? c[mi][ni][r * 2 + 0] : -1e9f;
                o.y = mk.y ? c[mi][ni][r * 2 + 1] : -1e9f;
                *(float2*)(arow + (size_t)i * L + j) = o;
            }
        }
}

// ---------------------------------------------------------------------------
// Softmax: one block per row (2048 elems), 256 threads x 8 elems, in place.
// ---------------------------------------------------------------------------
__global__ __launch_bounds__(256) void softmax_rows(float* __restrict__ att)
{
    float* p = att + (size_t)blockIdx.x * L;
    const int tid = threadIdx.x;
    float4 v0 = ((const float4*)p)[tid];
    float4 v1 = ((const float4*)p)[tid + 256];

    __shared__ float red[256];
    float m = fmaxf(fmaxf(fmaxf(v0.x, v0.y), fmaxf(v0.z, v0.w)),
                    fmaxf(fmaxf(v1.x, v1.y), fmaxf(v1.z, v1.w)));
    red[tid] = m;
    __syncthreads();
#pragma unroll
    for (int s = 128; s > 0; s >>= 1) {
        if (tid < s) red[tid] = fmaxf(red[tid], red[tid + s]);
        __syncthreads();
    }
    m = red[0];
    __syncthreads();

    float4 e0, e1;
    e0.x = expf(v0.x - m); e0.y = expf(v0.y - m);
    e0.z = expf(v0.z - m); e0.w = expf(v0.w - m);
    e1.x = expf(v1.x - m); e1.y = expf(v1.y - m);
    e1.z = expf(v1.z - m); e1.w = expf(v1.w - m);
    float lsum = (e0.x + e0.y) + (e0.z + e0.w) + (e1.x + e1.y) + (e1.z + e1.w);
    red[tid] = lsum;
    __syncthreads();
#pragma unroll
    for (int s = 128; s > 0; s >>= 1) {
        if (tid < s) red[tid] += red[tid + s];
        __syncthreads();
    }
    float inv = 1.f / red[0];

    e0.x *= inv; e0.y *= inv; e0.z *= inv; e0.w *= inv;
    e1.x *= inv; e1.y *= inv; e1.z *= inv; e1.w *= inv;
    ((float4*)p)[tid]       = e0;
    ((float4*)p)[tid + 256] = e1;
}

// ---------------------------------------------------------------------------
// GEMM 3: OutH[b*L+i, h*64+d] = sum_j att[bh,i,j] * Vh[bh,j,d]
// Per bh: M=2048, N=64, K=2048.  Block 128x64, ktile 32, 8 warps (4x2),
// warp 32x32.  P smem [m][k] pad36, V smem [k][n] pad68.
// ---------------------------------------------------------------------------
__global__ __launch_bounds__(256) void gemm_av(const float* __restrict__ att)
{
    __shared__ uint32_t Ps[128][36];
    __shared__ uint32_t Vs[32][68];
    const int tid = threadIdx.x;
    const int lane = tid & 31, w = tid >> 5;
    const int g = lane >> 2, tg = lane & 3;
    const int wm = (w >> 1) * 32;       // 0,32,64,96
    const int wn = (w & 1) * 32;        // 0,32
    const int bh = blockIdx.y, b = bh >> 4, h = bh & 15;
    const int i0 = blockIdx.x * 128;
    const float* Ab = att + (size_t)bh * L * L;
    const float* Vb = g_Vh + (size_t)bh * L * DH;

    float c[2][4][4];
#pragma unroll
    for (int mi = 0; mi < 2; mi++)
#pragma unroll
        for (int ni = 0; ni < 4; ni++)
#pragma unroll
            for (int r = 0; r < 4; r++) c[mi][ni][r] = 0.f;

    for (int k0 = 0; k0 < L; k0 += 32) {
#pragma unroll
        for (int t = 0; t < 4; t++) {           // P tile 128x32
            int idx = tid + t * 256;
            int row = idx >> 3, cc = (idx & 7) * 4;
            float4 v = *(const float4*)(Ab + (size_t)(i0 + row) * L + k0 + cc);
            Ps[row][cc + 0] = f2tf(v.x); Ps[row][cc + 1] = f2tf(v.y);
            Ps[row][cc + 2] = f2tf(v.z); Ps[row][cc + 3] = f2tf(v.w);
        }
#pragma unroll
        for (int t = 0; t < 2; t++) {           // V tile 32x64
            int idx = tid + t * 256;
            int row = idx >> 4, cc = (idx & 15) * 4;
            float4 v = *(const float4*)(Vb + (size_t)(k0 + row) * DH + cc);
            Vs[row][cc + 0] = f2tf(v.x); Vs[row][cc + 1] = f2tf(v.y);
            Vs[row][cc + 2] = f2tf(v.z); Vs[row][cc + 3] = f2tf(v.w);
        }
        __syncthreads();
#pragma unroll
        for (int kk = 0; kk < 32; kk += 8) {
            uint32_t a[2][4], bb[4][2];
#pragma unroll
            for (int mi = 0; mi < 2; mi++) {
                int m = wm + mi * 16 + g;
                a[mi][0] = Ps[m][kk + tg];
                a[mi][1] = Ps[m + 8][kk + tg];
                a[mi][2] = Ps[m][kk + tg + 4];
                a[mi][3] = Ps[m + 8][kk + tg + 4];
            }
#pragma unroll
            for (int ni = 0; ni < 4; ni++) {
                int n = wn + ni * 8 + g;
                bb[ni][0] = Vs[kk + tg][n];
                bb[ni][1] = Vs[kk + tg + 4][n];
            }
#pragma unroll
            for (int mi = 0; mi < 2; mi++)
#pragma unroll
                for (int ni = 0; ni < 4; ni++)
                    mma8(c[mi][ni], a[mi], bb[ni]);
        }
        __syncthreads();
    }
#pragma unroll
    for (int mi = 0; mi < 2; mi++)
#pragma unroll
        for (int r = 0; r < 2; r++) {
            int m = i0 + wm + mi * 16 + g + r * 8;
#pragma unroll
            for (int ni = 0; ni < 4; ni++) {
                int d = wn + ni * 8 + tg * 2;
                float2 o = {c[mi][ni][r * 2 + 0], c[mi][ni][r * 2 + 1]};
                *(float2*)&g_OutH[(size_t)(b * L + m) * D + h * DH + d] = o;
            }
        }
}

// ---------------------------------------------------------------------------
// GEMM 4: out = OutH @ Wfc + bfc + q   (M=8192, N=1024, K=1024)
// ---------------------------------------------------------------------------
__global__ __launch_bounds__(256) void gemm_fc(
    const float* __restrict__ Xres, const float* __restrict__ W,
    const float* __restrict__ bias, float* __restrict__ Out)
{
    __shared__ uint32_t As[128][36];
    __shared__ uint32_t Bs[32][132];
    const int tid = threadIdx.x;
    const int lane = tid & 31, w = tid >> 5;
    const int g = lane >> 2, tg = lane & 3;
    const int wm = (w >> 2) * 64, wn = (w & 3) * 32;
    const int m0 = blockIdx.y * 128;
    const int n0 = blockIdx.x * 128;

    float c[4][4][4];
#pragma unroll
    for (int mi = 0; mi < 4; mi++)
#pragma unroll
        for (int ni = 0; ni < 4; ni++)
#pragma unroll
            for (int r = 0; r < 4; r++) c[mi][ni][r] = 0.f;

    for (int k0 = 0; k0 < D; k0 += 32) {
#pragma unroll
        for (int t = 0; t < 4; t++) {
            int idx = tid + t * 256;
            int row = idx >> 3, cc = (idx & 7) * 4;
            float4 v = *(const float4*)(g_OutH + (size_t)(m0 + row) * D + k0 + cc);
            As[row][cc + 0] = f2tf(v.x); As[row][cc + 1] = f2tf(v.y);
            As[row][cc + 2] = f2tf(v.z); As[row][cc + 3] = f2tf(v.w);
        }
#pragma unroll
        for (int t = 0; t < 4; t++) {
            int idx = tid + t * 256;
            int row = idx >> 5, cc = (idx & 31) * 4;
            float4 v = *(const float4*)(W + (size_t)(k0 + row) * D + n0 + cc);
            Bs[row][cc + 0] = f2tf(v.x); Bs[row][cc + 1] = f2tf(v.y);
            Bs[row][cc + 2] = f2tf(v.z); Bs[row][cc + 3] = f2tf(v.w);
        }
        __syncthreads();
#pragma unroll
        for (int kk = 0; kk < 32; kk += 8) {
            uint32_t a[4][4], bb[4][2];
#pragma unroll
            for (int mi = 0; mi < 4; mi++) {
                int m = wm + mi * 16 + g;
                a[mi][0] = As[m][kk + tg];
                a[mi][1] = As[m + 8][kk + tg];
                a[mi][2] = As[m][kk + tg + 4];
                a[mi][3] = As[m + 8][kk + tg + 4];
            }
#pragma unroll
            for (int ni = 0; ni < 4; ni++) {
                int n = wn + ni * 8 + g;
                bb[ni][0] = Bs[kk + tg][n];
                bb[ni][1] = Bs[kk + tg + 4][n];
            }
#pragma unroll
            for (int mi = 0; mi < 4; mi++)
#pragma unroll
                for (int ni = 0; ni < 4; ni++)
                    mma8(c[mi][ni], a[mi], bb[ni]);
        }
        __syncthreads();
    }
#pragma unroll
    for (int mi = 0; mi < 4; mi++)
#pragma unroll
        for (int r = 0; r < 2; r++) {
            int gm = m0 + wm + mi * 16 + g + r * 8;
#pragma unroll
            for (int ni = 0; ni < 4; ni++) {
                int gn = n0 + wn + ni * 8 + tg * 2;
                float2 res = *(const float2*)(Xres + (size_t)gm * D + gn);
                float2 o;
                o.x = c[mi][ni][r * 2 + 0] + bias[gn]     + res.x;
                o.y = c[mi][ni][r * 2 + 1] + bias[gn + 1] + res.y;
                *(float2*)&Out[(size_t)gm * D + gn] = o;
            }
        }
}

// ---------------------------------------------------------------------------
extern "C" void kernel_launch(void* const* d_in, const int* in_sizes, int n_in,
                              void* d_out, int out_size)
{
    const float* q    = (const float*)d_in[0];
    const float* k    = (const float*)d_in[1];
    const float* v    = (const float*)d_in[2];
    const int*   mask = (const int*)d_in[3];
    const float* Wq   = (const float*)d_in[4];
    const float* bq   = (const float*)d_in[5];
    const float* Wk   = (const float*)d_in[6];
    const float* bk   = (const float*)d_in[7];
    const float* Wv   = (const float*)d_in[8];
    const float* bv   = (const float*)d_in[9];
    const float* Wfc  = (const float*)d_in[10];
    const float* bfc  = (const float*)d_in[11];

    float* out = (float*)d_out;                      // [B, L, D]
    float* att = out + (size_t)B * L * D;            // [B, H, L, L]

    float *Qh = nullptr, *Kh = nullptr, *Vh = nullptr;
    cudaGetSymbolAddress((void**)&Qh, g_Qh);
    cudaGetSymbolAddress((void**)&Kh, g_Kh);
    cudaGetSymbolAddress((void**)&Vh, g_Vh);

    dim3 gp(D / 128, ML / 128);       // (8, 64)
    gemm_proj<<<gp, 256>>>(q, Wq, bq, Qh, 0.125f);   // fold 1/TEMP into Q
    gemm_proj<<<gp, 256>>>(k, Wk, bk, Kh, 1.0f);
    gemm_proj<<<gp, 256>>>(v, Wv, bv, Vh, 1.0f);

    dim3 gs(L / 128, L / 128, BH);    // (16, 16, 64)
    gemm_scores<<<gs, 256>>>(mask, att);

    softmax_rows<<<BH * L, 256>>>(att);              // 131072 rows

    dim3 ga(L / 128, BH);             // (16, 64)
    gemm_av<<<ga, 256>>>(att);

    gemm_fc<<<gp, 256>>>(q, Wfc, bfc, out);
}